// round 6
// baseline (speedup 1.0000x reference)
#include <cuda_runtime.h>
#include <math.h>

// ---------------------------------------------------------------------------
// Augmentation3d: affine (Rodrigues * scale + shift) + smoothed random
// displacement field + trilinear grid_sample, cropped to center 128^3.
//
// Inputs (metadata order):
//   d_in[0] vol   : (4,1,160,160,160) f32
//   d_in[1] rot   : (4,3) f32
//   d_in[2] scale : (4,3) f32
//   d_in[3] shift : (4,3) f32
//   d_in[4] dz    : (1,1,15,15,15) f32
//   d_in[5] dy    : (1,1,15,15,15) f32
//   d_in[6] dx    : (1,1,15,15,15) f32
// Output: (4,1,128,128,128) f32
// ---------------------------------------------------------------------------

#define VD 160
#define VSZ (VD * VD * VD)
#define OD 128
#define CROP0 16            // (160-128)/2
#define FDIM 15
#define FN (FDIM * FDIM * FDIM)   // 3375
#define FS 11
#define FS3 (FS * FS * FS)        // 1331
#define NBATCH 4

__device__ float g_field[3][FS3];     // cropped smoothed fields (dz, dy, dx)
__device__ float g_theta[NBATCH * 12]; // per batch: 3 rows of [A0 A1 A2 shift]

// ---------------------------------------------------------------------------
// Prep kernel: 3 blocks (one per field). Separable clamped 5-tap box x4 iters.
// Block 0 additionally computes theta for the 4 batches.
// ---------------------------------------------------------------------------
__global__ void prep_kernel(const float* __restrict__ rot,
                            const float* __restrict__ scale,
                            const float* __restrict__ shift,
                            const float* __restrict__ dz,
                            const float* __restrict__ dy,
                            const float* __restrict__ dx) {
    __shared__ float bufA[FN];
    __shared__ float bufB[FN];

    const int f = blockIdx.x;
    const float* raw = (f == 0) ? dz : ((f == 1) ? dy : dx);
    const int t = threadIdx.x;
    const int NT = blockDim.x;

    for (int i = t; i < FN; i += NT)
        bufA[i] = (raw[i] - 0.5f) * 4.0f;   // (raw-0.5)*2*ALPHA, ALPHA=2
    __syncthreads();

    float* cur = bufA;
    float* nxt = bufB;

    for (int it = 0; it < 4; ++it) {
        // --- x pass ---
        for (int i = t; i < FN; i += NT) {
            int x = i % FDIM;
            int base = i - x;
            float s = 0.0f;
            #pragma unroll
            for (int k = -2; k <= 2; ++k) {
                int xi = x + k;
                xi = xi < 0 ? 0 : (xi > FDIM - 1 ? FDIM - 1 : xi);
                s += cur[base + xi];
            }
            nxt[i] = s * 0.2f;
        }
        __syncthreads();
        { float* tmp = cur; cur = nxt; nxt = tmp; }
        // --- y pass ---
        for (int i = t; i < FN; i += NT) {
            int x = i % FDIM;
            int y = (i / FDIM) % FDIM;
            int zb = i - y * FDIM - x;   // z*225 + x offset base
            float s = 0.0f;
            #pragma unroll
            for (int k = -2; k <= 2; ++k) {
                int yi = y + k;
                yi = yi < 0 ? 0 : (yi > FDIM - 1 ? FDIM - 1 : yi);
                s += cur[zb + yi * FDIM + x];
            }
            nxt[i] = s * 0.2f;
        }
        __syncthreads();
        { float* tmp = cur; cur = nxt; nxt = tmp; }
        // --- z pass ---
        for (int i = t; i < FN; i += NT) {
            int xy = i % (FDIM * FDIM);
            int z = i / (FDIM * FDIM);
            float s = 0.0f;
            #pragma unroll
            for (int k = -2; k <= 2; ++k) {
                int zi = z + k;
                zi = zi < 0 ? 0 : (zi > FDIM - 1 ? FDIM - 1 : zi);
                s += cur[zi * FDIM * FDIM + xy];
            }
            nxt[i] = s * 0.2f;
        }
        __syncthreads();
        { float* tmp = cur; cur = nxt; nxt = tmp; }
    }

    // crop [2:13]^3 -> 11^3 and publish
    for (int i = t; i < FS3; i += NT) {
        int x = i % FS;
        int y = (i / FS) % FS;
        int z = i / (FS * FS);
        g_field[f][i] = cur[(z + 2) * FDIM * FDIM + (y + 2) * FDIM + (x + 2)];
    }

    // theta (block 0, threads 0..3)
    if (f == 0 && t < NBATCH) {
        const int nb = t;
        float rx = rot[nb * 3 + 0], ry = rot[nb * 3 + 1], rz = rot[nb * 3 + 2];
        float t2 = rx * rx + ry * ry + rz * rz;
        float th = sqrtf(fmaxf(t2, 1e-6f));
        float inv = 1.0f / (th + 1e-6f);
        float wx = rx * inv, wy = ry * inv, wz = rz * inv;
        float c = cosf(th), s = sinf(th), k = 1.0f - c;
        float R[9];
        if (t2 > 1e-6f) {
            R[0] = c + wx * wx * k;   R[1] = wx * wy * k - wz * s; R[2] = wy * s + wx * wz * k;
            R[3] = wz * s + wx * wy * k; R[4] = c + wy * wy * k;   R[5] = -wx * s + wy * wz * k;
            R[6] = -wy * s + wx * wz * k; R[7] = wx * s + wy * wz * k; R[8] = c + wz * wz * k;
        } else {
            R[0] = 1.0f; R[1] = -rz;  R[2] = ry;
            R[3] = rz;   R[4] = 1.0f; R[5] = -rx;
            R[6] = -ry;  R[7] = rx;   R[8] = 1.0f;
        }
        #pragma unroll
        for (int i = 0; i < 3; ++i) {
            #pragma unroll
            for (int j = 0; j < 3; ++j)
                g_theta[nb * 12 + i * 4 + j] = R[i * 3 + j] * scale[nb * 3 + j];
            g_theta[nb * 12 + i * 4 + 3] = shift[nb * 3 + i];
        }
    }
}

// ---------------------------------------------------------------------------
// Main kernel: one thread per output voxel. Block = one x-row (128 threads,
// fixed n,z,y) so the z/y part of the field resize is shared across the block.
// ---------------------------------------------------------------------------
__global__ void __launch_bounds__(128) sample_kernel(
    const float* __restrict__ vol, float* __restrict__ out) {
    const int x = threadIdx.x;               // 0..127
    const int y = blockIdx.y;                // 0..127
    const int nz = blockIdx.z;               // n*128 + z
    const int n = nz >> 7;
    const int z = nz & 127;

    const int xg = x + CROP0;
    const int yg = y + CROP0;
    const int zg = z + CROP0;

    __shared__ float Gf[3][FS + 1];   // per-x-cell field value (z,y pre-reduced)
    __shared__ float th[12];

    const float SCL = 11.0f / 160.0f;   // exact in fp32

    // z/y source coords for the 11^3 -> 160 resize (uniform per block)
    float zsrc = fminf(fmaxf(((float)zg + 0.5f) * SCL - 0.5f, 0.0f), (float)(FS - 1));
    float ysrc = fminf(fmaxf(((float)yg + 0.5f) * SCL - 0.5f, 0.0f), (float)(FS - 1));
    int iz0 = (int)floorf(zsrc);  float wz = zsrc - (float)iz0;  int iz1 = min(iz0 + 1, FS - 1);
    int iy0 = (int)floorf(ysrc);  float wy = ysrc - (float)iy0;  int iy1 = min(iy0 + 1, FS - 1);

    if (threadIdx.x < 3 * FS) {
        int f = threadIdx.x / FS;
        int ix = threadIdx.x - f * FS;
        const float* F = g_field[f];
        float v00 = __ldg(&F[(iz0 * FS + iy0) * FS + ix]);
        float v01 = __ldg(&F[(iz0 * FS + iy1) * FS + ix]);
        float v10 = __ldg(&F[(iz1 * FS + iy0) * FS + ix]);
        float v11 = __ldg(&F[(iz1 * FS + iy1) * FS + ix]);
        Gf[f][ix] = (1.0f - wz) * ((1.0f - wy) * v00 + wy * v01)
                  + wz * ((1.0f - wy) * v10 + wy * v11);
    }
    if (threadIdx.x < 12) th[threadIdx.x] = g_theta[n * 12 + threadIdx.x];
    __syncthreads();

    // per-thread x lerp of the three fields
    float xsrc = fminf(fmaxf(((float)xg + 0.5f) * SCL - 0.5f, 0.0f), (float)(FS - 1));
    int ix0 = (int)floorf(xsrc);  float wxf = xsrc - (float)ix0;  int ix1 = min(ix0 + 1, FS - 1);
    float fdz = Gf[0][ix0] * (1.0f - wxf) + Gf[0][ix1] * wxf;
    float fdy = Gf[1][ix0] * (1.0f - wxf) + Gf[1][ix1] * wxf;
    float fdx = Gf[2][ix0] * (1.0f - wxf) + Gf[2][ix1] * wxf;

    // normalized coords of this output voxel in the 160 grid
    float xv = (2.0f * (float)xg + 1.0f) / 160.0f - 1.0f;
    float yv = (2.0f * (float)yg + 1.0f) / 160.0f - 1.0f;
    float zv = (2.0f * (float)zg + 1.0f) / 160.0f - 1.0f;

    // grid = theta * [x,y,z,1] + disp  (disp[...,0]=field(dz) -> x coord, etc.)
    float gx = th[0] * xv + th[1] * yv + th[2]  * zv + th[3]  + fdz;
    float gy = th[4] * xv + th[5] * yv + th[6]  * zv + th[7]  + fdy;
    float gz = th[8] * xv + th[9] * yv + th[10] * zv + th[11] + fdx;

    // grid_sample (align_corners=False): p = ((g+1)*S - 1)*0.5
    float px = gx * 80.0f + 79.5f;
    float py = gy * 80.0f + 79.5f;
    float pz = gz * 80.0f + 79.5f;

    float fx0 = floorf(px), fy0 = floorf(py), fz0 = floorf(pz);
    float ax = px - fx0, ay = py - fy0, az = pz - fz0;
    int x0 = (int)fx0, y0 = (int)fy0, z0 = (int)fz0;
    int x1 = x0 + 1, y1 = y0 + 1, z1 = z0 + 1;

    const float* v = vol + (size_t)n * VSZ;

    auto at = [&](int zi, int yi, int xi) -> float {
        if ((unsigned)zi < (unsigned)VD && (unsigned)yi < (unsigned)VD &&
            (unsigned)xi < (unsigned)VD)
            return __ldg(&v[((size_t)zi * VD + yi) * VD + xi]);
        return 0.0f;
    };

    float bx0 = 1.0f - ax, by0 = 1.0f - ay, bz0 = 1.0f - az;

    float r = 0.0f;
    r += at(z0, y0, x0) * (bz0 * by0 * bx0);
    r += at(z0, y0, x1) * (bz0 * by0 * ax);
    r += at(z0, y1, x0) * (bz0 * ay * bx0);
    r += at(z0, y1, x1) * (bz0 * ay * ax);
    r += at(z1, y0, x0) * (az * by0 * bx0);
    r += at(z1, y0, x1) * (az * by0 * ax);
    r += at(z1, y1, x0) * (az * ay * bx0);
    r += at(z1, y1, x1) * (az * ay * ax);

    out[(((size_t)n * OD + z) * OD + y) * OD + x] = r;
}

// ---------------------------------------------------------------------------
extern "C" void kernel_launch(void* const* d_in, const int* in_sizes, int n_in,
                              void* d_out, int out_size) {
    const float* vol   = (const float*)d_in[0];
    const float* rot   = (const float*)d_in[1];
    const float* scale = (const float*)d_in[2];
    const float* shift = (const float*)d_in[3];
    const float* dz    = (const float*)d_in[4];
    const float* dy    = (const float*)d_in[5];
    const float* dx    = (const float*)d_in[6];
    float* out = (float*)d_out;

    prep_kernel<<<3, 1024>>>(rot, scale, shift, dz, dy, dx);

    dim3 grid(1, OD, NBATCH * OD);
    sample_kernel<<<grid, 128>>>(vol, out);
}

// round 7
// speedup vs baseline: 1.1571x; 1.1571x over previous
#include <cuda_runtime.h>
#include <math.h>

// ---------------------------------------------------------------------------
// Augmentation3d: affine (Rodrigues * scale + shift) + smoothed random
// displacement field + trilinear grid_sample, cropped to center 128^3.
//
// Inputs (metadata order):
//   d_in[0] vol   : (4,1,160,160,160) f32
//   d_in[1] rot   : (4,3) f32
//   d_in[2] scale : (4,3) f32
//   d_in[3] shift : (4,3) f32
//   d_in[4] dz    : (1,1,15,15,15) f32
//   d_in[5] dy    : (1,1,15,15,15) f32
//   d_in[6] dx    : (1,1,15,15,15) f32
// Output: (4,1,128,128,128) f32
// ---------------------------------------------------------------------------

#define VD 160
#define VSZ (VD * VD * VD)
#define OD 128
#define CROP0 16            // (160-128)/2
#define FDIM 15
#define FN (FDIM * FDIM * FDIM)   // 3375
#define FS 11
#define FS3 (FS * FS * FS)        // 1331
#define NBATCH 4

__device__ float g_field[3][FS3];      // cropped smoothed fields (dz, dy, dx)
__device__ float g_theta[NBATCH * 12]; // per batch: 3 rows of [A0 A1 A2 shift]

// ---------------------------------------------------------------------------
// Prep kernel (single block): the 4x clamped 5-tap box smooth is a fixed
// linear operator per axis -> build B^4 (15x15) once in smem, then apply as
// three tiny separable matmuls (with the [2:13] crop folded into the z/y/x
// output rows). Also computes theta for the 4 batches.
// ---------------------------------------------------------------------------
__global__ void __launch_bounds__(1024) prep_kernel(
        const float* __restrict__ rot,
        const float* __restrict__ scale,
        const float* __restrict__ shift,
        const float* __restrict__ dz,
        const float* __restrict__ dy,
        const float* __restrict__ dx) {
    __shared__ float Bm[FDIM][FDIM];   // clamped box matrix
    __shared__ float B2[FDIM][FDIM];   // B^2
    __shared__ float M[FS][FDIM];      // rows 2..12 of B^4 (crop folded)
    __shared__ float bufA[FN];         // 3375
    __shared__ float bufB[FS * FDIM * FDIM]; // 2475

    const int t = threadIdx.x;
    const int NT = blockDim.x;

    // --- theta (threads 0..3, independent of field work) ---
    if (t < NBATCH) {
        const int nb = t;
        float rx = rot[nb * 3 + 0], ry = rot[nb * 3 + 1], rz = rot[nb * 3 + 2];
        float t2 = rx * rx + ry * ry + rz * rz;
        float th = sqrtf(fmaxf(t2, 1e-6f));
        float inv = 1.0f / (th + 1e-6f);
        float wx = rx * inv, wy = ry * inv, wz = rz * inv;
        float c = cosf(th), s = sinf(th), k = 1.0f - c;
        float R[9];
        if (t2 > 1e-6f) {
            R[0] = c + wx * wx * k;      R[1] = wx * wy * k - wz * s; R[2] = wy * s + wx * wz * k;
            R[3] = wz * s + wx * wy * k; R[4] = c + wy * wy * k;      R[5] = -wx * s + wy * wz * k;
            R[6] = -wy * s + wx * wz * k; R[7] = wx * s + wy * wz * k; R[8] = c + wz * wz * k;
        } else {
            R[0] = 1.0f; R[1] = -rz;  R[2] = ry;
            R[3] = rz;   R[4] = 1.0f; R[5] = -rx;
            R[6] = -ry;  R[7] = rx;   R[8] = 1.0f;
        }
        #pragma unroll
        for (int i = 0; i < 3; ++i) {
            #pragma unroll
            for (int j = 0; j < 3; ++j)
                g_theta[nb * 12 + i * 4 + j] = R[i * 3 + j] * scale[nb * 3 + j];
            g_theta[nb * 12 + i * 4 + 3] = shift[nb * 3 + i];
        }
    }

    // --- build B (clamped box), B^2, then M = (B^4)[2:13,:] ---
    if (t < FDIM * FDIM) {
        int i = t / FDIM, j = t % FDIM;
        int cnt = 0;
        #pragma unroll
        for (int d = -2; d <= 2; ++d) {
            int k = i + d;
            k = k < 0 ? 0 : (k > FDIM - 1 ? FDIM - 1 : k);
            cnt += (k == j);
        }
        Bm[i][j] = 0.2f * (float)cnt;
    }
    __syncthreads();
    if (t < FDIM * FDIM) {
        int i = t / FDIM, j = t % FDIM;
        float s = 0.0f;
        #pragma unroll
        for (int k = 0; k < FDIM; ++k) s += Bm[i][k] * Bm[k][j];
        B2[i][j] = s;
    }
    __syncthreads();
    if (t < FS * FDIM) {
        int i = t / FDIM + 2, j = t % FDIM;   // rows 2..12
        float s = 0.0f;
        #pragma unroll
        for (int k = 0; k < FDIM; ++k) s += B2[i][k] * B2[k][j];
        M[i - 2][j] = s;
    }

    // --- per-field separable application ---
    for (int f = 0; f < 3; ++f) {
        const float* raw = (f == 0) ? dz : ((f == 1) ? dy : dx);
        __syncthreads();
        for (int i = t; i < FN; i += NT)
            bufA[i] = (raw[i] - 0.5f) * 4.0f;       // (raw-0.5)*2*ALPHA
        __syncthreads();
        // z-pass: [15,15,15] -> [11,15,15]
        for (int i = t; i < FS * FDIM * FDIM; i += NT) {
            int xy = i % (FDIM * FDIM);
            int zo = i / (FDIM * FDIM);
            float s = 0.0f;
            #pragma unroll
            for (int k = 0; k < FDIM; ++k)
                s += M[zo][k] * bufA[k * FDIM * FDIM + xy];
            bufB[i] = s;
        }
        __syncthreads();
        // y-pass: [11,15,15] -> [11,11,15] (into bufA)
        for (int i = t; i < FS * FS * FDIM; i += NT) {
            int x = i % FDIM;
            int yo = (i / FDIM) % FS;
            int zo = i / (FDIM * FS);
            float s = 0.0f;
            #pragma unroll
            for (int k = 0; k < FDIM; ++k)
                s += M[yo][k] * bufB[zo * FDIM * FDIM + k * FDIM + x];
            bufA[zo * FS * FDIM + yo * FDIM + x] = s;
        }
        __syncthreads();
        // x-pass: [11,11,15] -> [11,11,11] (to global)
        for (int i = t; i < FS3; i += NT) {
            int xo = i % FS;
            int yo = (i / FS) % FS;
            int zo = i / (FS * FS);
            float s = 0.0f;
            #pragma unroll
            for (int k = 0; k < FDIM; ++k)
                s += M[xo][k] * bufA[zo * FS * FDIM + yo * FDIM + k];
            g_field[f][i] = s;
        }
    }
}

// ---------------------------------------------------------------------------
// Main kernel: one thread per output voxel. Block = one x-row (128 threads,
// fixed n,z,y) so the z/y part of the field resize is shared across the block.
// Gather addressing: single base index + constant offsets (folded into LDG
// immediates); per-axis validity predicates; nested-lerp trilinear blend.
// ---------------------------------------------------------------------------
__global__ void __launch_bounds__(128) sample_kernel(
    const float* __restrict__ vol, float* __restrict__ out) {
    const int x = threadIdx.x;               // 0..127
    const int y = blockIdx.y;                // 0..127
    const int nz = blockIdx.z;               // n*128 + z
    const int n = nz >> 7;
    const int z = nz & 127;

    const int xg = x + CROP0;
    const int yg = y + CROP0;
    const int zg = z + CROP0;

    __shared__ float Gf[3][FS + 1];   // per-x-cell field value (z,y pre-reduced)
    __shared__ float th[12];

    const float SCL = 11.0f / 160.0f;   // exact in fp32

    // z/y source coords for the 11^3 -> 160 resize (uniform per block)
    float zsrc = fminf(fmaxf(((float)zg + 0.5f) * SCL - 0.5f, 0.0f), (float)(FS - 1));
    float ysrc = fminf(fmaxf(((float)yg + 0.5f) * SCL - 0.5f, 0.0f), (float)(FS - 1));
    int iz0 = (int)floorf(zsrc);  float wz = zsrc - (float)iz0;  int iz1 = min(iz0 + 1, FS - 1);
    int iy0 = (int)floorf(ysrc);  float wy = ysrc - (float)iy0;  int iy1 = min(iy0 + 1, FS - 1);

    if (threadIdx.x < 3 * FS) {
        int f = threadIdx.x / FS;
        int ix = threadIdx.x - f * FS;
        const float* F = g_field[f];
        float v00 = __ldg(&F[(iz0 * FS + iy0) * FS + ix]);
        float v01 = __ldg(&F[(iz0 * FS + iy1) * FS + ix]);
        float v10 = __ldg(&F[(iz1 * FS + iy0) * FS + ix]);
        float v11 = __ldg(&F[(iz1 * FS + iy1) * FS + ix]);
        Gf[f][ix] = (1.0f - wz) * ((1.0f - wy) * v00 + wy * v01)
                  + wz * ((1.0f - wy) * v10 + wy * v11);
    }
    if (threadIdx.x < 12) th[threadIdx.x] = g_theta[n * 12 + threadIdx.x];
    __syncthreads();

    // per-thread x lerp of the three fields
    float xsrc = fminf(fmaxf(((float)xg + 0.5f) * SCL - 0.5f, 0.0f), (float)(FS - 1));
    int ix0 = (int)floorf(xsrc);  float wxf = xsrc - (float)ix0;  int ix1 = min(ix0 + 1, FS - 1);
    float fdz = Gf[0][ix0] + (Gf[0][ix1] - Gf[0][ix0]) * wxf;
    float fdy = Gf[1][ix0] + (Gf[1][ix1] - Gf[1][ix0]) * wxf;
    float fdx = Gf[2][ix0] + (Gf[2][ix1] - Gf[2][ix0]) * wxf;

    // normalized coords of this output voxel in the 160 grid
    float xv = (2.0f * (float)xg + 1.0f) * (1.0f / 160.0f) - 1.0f;
    float yv = (2.0f * (float)yg + 1.0f) * (1.0f / 160.0f) - 1.0f;
    float zv = (2.0f * (float)zg + 1.0f) * (1.0f / 160.0f) - 1.0f;

    // grid = theta * [x,y,z,1] + disp  (disp[...,0]=field(dz) -> x coord, etc.)
    float gx = fmaf(th[0], xv, fmaf(th[1], yv, fmaf(th[2],  zv, th[3]  + fdz)));
    float gy = fmaf(th[4], xv, fmaf(th[5], yv, fmaf(th[6],  zv, th[7]  + fdy)));
    float gz = fmaf(th[8], xv, fmaf(th[9], yv, fmaf(th[10], zv, th[11] + fdx)));

    // grid_sample (align_corners=False): p = ((g+1)*S - 1)*0.5
    float px = fmaf(gx, 80.0f, 79.5f);
    float py = fmaf(gy, 80.0f, 79.5f);
    float pz = fmaf(gz, 80.0f, 79.5f);

    int x0 = __float2int_rd(px);  float ax = px - (float)x0;
    int y0 = __float2int_rd(py);  float ay = py - (float)y0;
    int z0 = __float2int_rd(pz);  float az = pz - (float)z0;

    // per-axis validity (x1=x0+1 etc.)
    int vx0 = ((unsigned)x0 < (unsigned)VD);
    int vx1 = ((unsigned)(x0 + 1) < (unsigned)VD);
    int vy0 = ((unsigned)y0 < (unsigned)VD);
    int vy1 = ((unsigned)(y0 + 1) < (unsigned)VD);
    int vz0 = ((unsigned)z0 < (unsigned)VD);
    int vz1 = ((unsigned)(z0 + 1) < (unsigned)VD);

    int p00 = vz0 & vy0, p01 = vz0 & vy1, p10 = vz1 & vy0, p11 = vz1 & vy1;

    const float* v = vol + (size_t)n * VSZ;
    const int base = (z0 * VD + y0) * VD + x0;   // fits int32 for any reachable coord
    const float* vb = v + base;

    // 8 corner loads: one base address, constant offsets (LDG immediates),
    // predicated off when out of bounds (reads as 0).
    float v000 = (p00 & vx0) ? __ldg(vb)                    : 0.0f;
    float v001 = (p00 & vx1) ? __ldg(vb + 1)                : 0.0f;
    float v010 = (p01 & vx0) ? __ldg(vb + VD)               : 0.0f;
    float v011 = (p01 & vx1) ? __ldg(vb + VD + 1)           : 0.0f;
    float v100 = (p10 & vx0) ? __ldg(vb + VD * VD)          : 0.0f;
    float v101 = (p10 & vx1) ? __ldg(vb + VD * VD + 1)      : 0.0f;
    float v110 = (p11 & vx0) ? __ldg(vb + VD * VD + VD)     : 0.0f;
    float v111 = (p11 & vx1) ? __ldg(vb + VD * VD + VD + 1) : 0.0f;

    // nested-lerp trilinear blend (7 lerps)
    float c00 = fmaf(v001 - v000, ax, v000);
    float c01 = fmaf(v011 - v010, ax, v010);
    float c10 = fmaf(v101 - v100, ax, v100);
    float c11 = fmaf(v111 - v110, ax, v110);
    float c0  = fmaf(c01 - c00, ay, c00);
    float c1  = fmaf(c11 - c10, ay, c10);
    float r   = fmaf(c1 - c0, az, c0);

    out[(((size_t)n * OD + z) * OD + y) * OD + x] = r;
}

// ---------------------------------------------------------------------------
extern "C" void kernel_launch(void* const* d_in, const int* in_sizes, int n_in,
                              void* d_out, int out_size) {
    const float* vol   = (const float*)d_in[0];
    const float* rot   = (const float*)d_in[1];
    const float* scale = (const float*)d_in[2];
    const float* shift = (const float*)d_in[3];
    const float* dz    = (const float*)d_in[4];
    const float* dy    = (const float*)d_in[5];
    const float* dx    = (const float*)d_in[6];
    float* out = (float*)d_out;

    prep_kernel<<<1, 1024>>>(rot, scale, shift, dz, dy, dx);

    dim3 grid(1, OD, NBATCH * OD);
    sample_kernel<<<grid, 128>>>(vol, out);
}

// round 8
// speedup vs baseline: 1.4332x; 1.2386x over previous
#include <cuda_runtime.h>
#include <math.h>

// ---------------------------------------------------------------------------
// Augmentation3d: affine (Rodrigues * scale + shift) + smoothed random
// displacement field + trilinear grid_sample, cropped to center 128^3.
//
// Inputs (metadata order):
//   d_in[0] vol   : (4,1,160,160,160) f32
//   d_in[1] rot   : (4,3) f32
//   d_in[2] scale : (4,3) f32
//   d_in[3] shift : (4,3) f32
//   d_in[4] dz    : (1,1,15,15,15) f32
//   d_in[5] dy    : (1,1,15,15,15) f32
//   d_in[6] dx    : (1,1,15,15,15) f32
// Output: (4,1,128,128,128) f32
// ---------------------------------------------------------------------------

#define VD 160
#define VSZ (VD * VD * VD)
#define OD 128
#define CROP0 16            // (160-128)/2
#define FDIM 15
#define FN (FDIM * FDIM * FDIM)   // 3375
#define FS 11
#define FS3 (FS * FS * FS)        // 1331
#define NBATCH 4
#define KZ 8                 // z-slices per block in sample kernel
#define SCLF (11.0f / 160.0f)

__device__ float g_field[3][FS3];      // cropped smoothed fields (dz, dy, dx)
__device__ float g_theta[NBATCH * 12]; // per batch: 3 rows of [A0 A1 A2 shift]

// ---------------------------------------------------------------------------
// Prep kernel: 3 blocks (one per field). The 4x clamped 5-tap box smooth is a
// fixed linear operator per axis -> build B^4 (15x15) in smem (redundantly per
// block, it's tiny), then apply as three small separable matmuls with the
// [2:13] crop folded in. Block 0 also computes theta for the 4 batches.
// ---------------------------------------------------------------------------
__global__ void __launch_bounds__(1024) prep_kernel(
        const float* __restrict__ rot,
        const float* __restrict__ scale,
        const float* __restrict__ shift,
        const float* __restrict__ dz,
        const float* __restrict__ dy,
        const float* __restrict__ dx) {
    __shared__ float Bm[FDIM][FDIM];   // clamped box matrix
    __shared__ float B2[FDIM][FDIM];   // B^2
    __shared__ float M[FS][FDIM];      // rows 2..12 of B^4 (crop folded)
    __shared__ float bufA[FN];         // 3375
    __shared__ float bufB[FS * FDIM * FDIM]; // 2475

    const int f = blockIdx.x;
    const float* raw = (f == 0) ? dz : ((f == 1) ? dy : dx);
    const int t = threadIdx.x;
    const int NT = blockDim.x;

    // --- theta (block 0, threads 0..3) ---
    if (f == 0 && t < NBATCH) {
        const int nb = t;
        float rx = rot[nb * 3 + 0], ry = rot[nb * 3 + 1], rz = rot[nb * 3 + 2];
        float t2 = rx * rx + ry * ry + rz * rz;
        float th = sqrtf(fmaxf(t2, 1e-6f));
        float inv = 1.0f / (th + 1e-6f);
        float wx = rx * inv, wy = ry * inv, wz = rz * inv;
        float c = cosf(th), s = sinf(th), k = 1.0f - c;
        float R[9];
        if (t2 > 1e-6f) {
            R[0] = c + wx * wx * k;      R[1] = wx * wy * k - wz * s; R[2] = wy * s + wx * wz * k;
            R[3] = wz * s + wx * wy * k; R[4] = c + wy * wy * k;      R[5] = -wx * s + wy * wz * k;
            R[6] = -wy * s + wx * wz * k; R[7] = wx * s + wy * wz * k; R[8] = c + wz * wz * k;
        } else {
            R[0] = 1.0f; R[1] = -rz;  R[2] = ry;
            R[3] = rz;   R[4] = 1.0f; R[5] = -rx;
            R[6] = -ry;  R[7] = rx;   R[8] = 1.0f;
        }
        #pragma unroll
        for (int i = 0; i < 3; ++i) {
            #pragma unroll
            for (int j = 0; j < 3; ++j)
                g_theta[nb * 12 + i * 4 + j] = R[i * 3 + j] * scale[nb * 3 + j];
            g_theta[nb * 12 + i * 4 + 3] = shift[nb * 3 + i];
        }
    }

    // --- build B (clamped box), B^2, then M = (B^4)[2:13,:] ---
    if (t < FDIM * FDIM) {
        int i = t / FDIM, j = t % FDIM;
        int cnt = 0;
        #pragma unroll
        for (int d = -2; d <= 2; ++d) {
            int k = i + d;
            k = k < 0 ? 0 : (k > FDIM - 1 ? FDIM - 1 : k);
            cnt += (k == j);
        }
        Bm[i][j] = 0.2f * (float)cnt;
    }
    // load + pre-scale raw field concurrently
    for (int i = t; i < FN; i += NT)
        bufA[i] = (raw[i] - 0.5f) * 4.0f;       // (raw-0.5)*2*ALPHA
    __syncthreads();
    if (t < FDIM * FDIM) {
        int i = t / FDIM, j = t % FDIM;
        float s = 0.0f;
        #pragma unroll
        for (int k = 0; k < FDIM; ++k) s += Bm[i][k] * Bm[k][j];
        B2[i][j] = s;
    }
    __syncthreads();
    if (t < FS * FDIM) {
        int i = t / FDIM + 2, j = t % FDIM;   // rows 2..12
        float s = 0.0f;
        #pragma unroll
        for (int k = 0; k < FDIM; ++k) s += B2[i][k] * B2[k][j];
        M[i - 2][j] = s;
    }
    __syncthreads();

    // z-pass: [15,15,15] -> [11,15,15]
    for (int i = t; i < FS * FDIM * FDIM; i += NT) {
        int xy = i % (FDIM * FDIM);
        int zo = i / (FDIM * FDIM);
        float s = 0.0f;
        #pragma unroll
        for (int k = 0; k < FDIM; ++k)
            s += M[zo][k] * bufA[k * FDIM * FDIM + xy];
        bufB[i] = s;
    }
    __syncthreads();
    // y-pass: [11,15,15] -> [11,11,15] (into bufA)
    for (int i = t; i < FS * FS * FDIM; i += NT) {
        int x = i % FDIM;
        int yo = (i / FDIM) % FS;
        int zo = i / (FDIM * FS);
        float s = 0.0f;
        #pragma unroll
        for (int k = 0; k < FDIM; ++k)
            s += M[yo][k] * bufB[zo * FDIM * FDIM + k * FDIM + x];
        bufA[zo * FS * FDIM + yo * FDIM + x] = s;
    }
    __syncthreads();
    // x-pass: [11,11,15] -> [11,11,11] (to global)
    for (int i = t; i < FS3; i += NT) {
        int xo = i % FS;
        int yo = (i / FS) % FS;
        int zo = i / (FS * FS);
        float s = 0.0f;
        #pragma unroll
        for (int k = 0; k < FDIM; ++k)
            s += M[xo][k] * bufA[zo * FS * FDIM + yo * FDIM + k];
        g_field[f][i] = s;
    }
}

// ---------------------------------------------------------------------------
// Main kernel: block = one x-row (128 threads) x KZ z-slices. Per-thread
// affine/field-x setup is loop-invariant; per-z only the linear z term (+kz*t2
// per axis, since 80*t2*(2/160)=t2) and the staged field row change. Field
// staged pre-scaled by 80 as float4 per x-cell (3 fields packed) -> 2 LDS.128
// per output. Interior warps take an unpredicated fast path (warp vote).
// ---------------------------------------------------------------------------
__global__ void __launch_bounds__(128) sample_kernel(
    const float* __restrict__ vol, float* __restrict__ out) {
    const int x  = threadIdx.x;              // 0..127
    const int y  = blockIdx.y;               // 0..127
    const int g  = blockIdx.z;               // n*(128/KZ) + zgrp
    const int n  = g >> 4;                   // 128/KZ = 16
    const int zb = (g & 15) * KZ;            // output z base

    const int xg  = x + CROP0;
    const int yg  = y + CROP0;
    const int zgb = zb + CROP0;

    __shared__ float4 Gf4[2][12];            // staged field row (x80), dbl-buffered

    // theta (broadcast loads, loop-invariant)
    const float* T = g_theta + n * 12;
    const float t0 = __ldg(T + 0), t1 = __ldg(T + 1), t2 = __ldg(T + 2),  t3  = __ldg(T + 3);
    const float t4 = __ldg(T + 4), t5 = __ldg(T + 5), t6 = __ldg(T + 6),  t7  = __ldg(T + 7);
    const float t8 = __ldg(T + 8), t9 = __ldg(T + 9), t10= __ldg(T + 10), t11 = __ldg(T + 11);

    const float C2 = 2.0f / 160.0f;
    const float C1 = 1.0f / 160.0f - 1.0f;
    const float xv  = fmaf((float)xg,  C2, C1);
    const float yv  = fmaf((float)yg,  C2, C1);
    const float zv0 = fmaf((float)zgb, C2, C1);

    // px = 80*gx + 79.5 with gx = t0*xv + t1*yv + t2*zv + t3 + fdz
    // bx folds everything except the per-iter z step (kz*t2) and the field term.
    const float bx = fmaf(80.0f, fmaf(t0, xv, fmaf(t1, yv, fmaf(t2,  zv0, t3 ))), 79.5f);
    const float by = fmaf(80.0f, fmaf(t4, xv, fmaf(t5, yv, fmaf(t6,  zv0, t7 ))), 79.5f);
    const float bz = fmaf(80.0f, fmaf(t8, xv, fmaf(t9, yv, fmaf(t10, zv0, t11))), 79.5f);

    // field x-cell (per thread, loop-invariant; interior -> no clamp needed)
    const float xsrc = fmaf((float)xg + 0.5f, SCLF, -0.5f);   // in (0.6, 9.4)
    const int   ix0  = (int)xsrc;
    const float wxf  = xsrc - (float)ix0;

    // field y (block-uniform, loop-invariant)
    const float ysrc = fmaf((float)yg + 0.5f, SCLF, -0.5f);
    const int   iy0  = (int)ysrc;
    const float wy   = ysrc - (float)iy0;

    const float* v  = vol + (size_t)n * VSZ;
    float*       op = out + (((size_t)(n * OD + zb)) * OD + y) * OD + x;

    #pragma unroll 2
    for (int kz = 0; kz < KZ; ++kz) {
        float4* GB = Gf4[kz & 1];

        // stage field row for this z (threads 0..32: 3 fields x 11 x-cells)
        if (threadIdx.x < 3 * FS) {
            int f2 = threadIdx.x / FS;
            int ix = threadIdx.x - f2 * FS;
            float zsrc = fmaf((float)(zgb + kz) + 0.5f, SCLF, -0.5f);
            int   iz0  = (int)zsrc;
            float wz   = zsrc - (float)iz0;
            const float* F = g_field[f2] + (iz0 * FS + iy0) * FS + ix;
            float v00 = __ldg(F);
            float v01 = __ldg(F + FS);
            float v10 = __ldg(F + FS * FS);
            float v11 = __ldg(F + FS * FS + FS);
            float a = fmaf(v01 - v00, wy, v00);
            float b = fmaf(v11 - v10, wy, v10);
            ((float*)&GB[ix])[f2] = fmaf(b - a, wz, a) * 80.0f;
        }
        __syncthreads();

        float4 A = GB[ix0];
        float4 B = GB[ix0 + 1];
        float kf = (float)kz;
        float px = fmaf(kf, t2,  bx) + fmaf(B.x - A.x, wxf, A.x);
        float py = fmaf(kf, t6,  by) + fmaf(B.y - A.y, wxf, A.y);
        float pz = fmaf(kf, t10, bz) + fmaf(B.z - A.z, wxf, A.z);

        float fx = floorf(px), fy = floorf(py), fz = floorf(pz);
        float ax = px - fx, ay = py - fy, az = pz - fz;
        int x0 = (int)fx, y0 = (int)fy, z0 = (int)fz;

        const float* vb = v + (z0 * VD + y0) * VD + x0;
        float v000, v001, v010, v011, v100, v101, v110, v111;

        // interior iff 0 <= c <= VD-2 for all axes (covers both corners)
        int inb = ((unsigned)x0 < (unsigned)(VD - 1)) &
                  ((unsigned)y0 < (unsigned)(VD - 1)) &
                  ((unsigned)z0 < (unsigned)(VD - 1));
        if (__all_sync(0xffffffffu, inb)) {
            v000 = __ldg(vb);                    v001 = __ldg(vb + 1);
            v010 = __ldg(vb + VD);               v011 = __ldg(vb + VD + 1);
            v100 = __ldg(vb + VD * VD);          v101 = __ldg(vb + VD * VD + 1);
            v110 = __ldg(vb + VD * VD + VD);     v111 = __ldg(vb + VD * VD + VD + 1);
        } else {
            int vx0 = ((unsigned)x0 < (unsigned)VD);
            int vx1 = ((unsigned)(x0 + 1) < (unsigned)VD);
            int vy0 = ((unsigned)y0 < (unsigned)VD);
            int vy1 = ((unsigned)(y0 + 1) < (unsigned)VD);
            int vz0 = ((unsigned)z0 < (unsigned)VD);
            int vz1 = ((unsigned)(z0 + 1) < (unsigned)VD);
            int p00 = vz0 & vy0, p01 = vz0 & vy1, p10 = vz1 & vy0, p11 = vz1 & vy1;
            v000 = (p00 & vx0) ? __ldg(vb)                    : 0.0f;
            v001 = (p00 & vx1) ? __ldg(vb + 1)                : 0.0f;
            v010 = (p01 & vx0) ? __ldg(vb + VD)               : 0.0f;
            v011 = (p01 & vx1) ? __ldg(vb + VD + 1)           : 0.0f;
            v100 = (p10 & vx0) ? __ldg(vb + VD * VD)          : 0.0f;
            v101 = (p10 & vx1) ? __ldg(vb + VD * VD + 1)      : 0.0f;
            v110 = (p11 & vx0) ? __ldg(vb + VD * VD + VD)     : 0.0f;
            v111 = (p11 & vx1) ? __ldg(vb + VD * VD + VD + 1) : 0.0f;
        }

        // nested-lerp trilinear blend
        float c00 = fmaf(v001 - v000, ax, v000);
        float c01 = fmaf(v011 - v010, ax, v010);
        float c10 = fmaf(v101 - v100, ax, v100);
        float c11 = fmaf(v111 - v110, ax, v110);
        float c0  = fmaf(c01 - c00, ay, c00);
        float c1  = fmaf(c11 - c10, ay, c10);
        float r   = fmaf(c1 - c0, az, c0);

        *op = r;
        op += OD * OD;
        __syncthreads();   // protect GB double-buffer reuse (cheap named bar)
    }
}

// ---------------------------------------------------------------------------
extern "C" void kernel_launch(void* const* d_in, const int* in_sizes, int n_in,
                              void* d_out, int out_size) {
    const float* vol   = (const float*)d_in[0];
    const float* rot   = (const float*)d_in[1];
    const float* scale = (const float*)d_in[2];
    const float* shift = (const float*)d_in[3];
    const float* dz    = (const float*)d_in[4];
    const float* dy    = (const float*)d_in[5];
    const float* dx    = (const float*)d_in[6];
    float* out = (float*)d_out;

    prep_kernel<<<3, 1024>>>(rot, scale, shift, dz, dy, dx);

    dim3 grid(1, OD, NBATCH * (OD / KZ));
    sample_kernel<<<grid, 128>>>(vol, out);
}

// round 9
// speedup vs baseline: 1.5462x; 1.0788x over previous
#include <cuda_runtime.h>
#include <math.h>

// ---------------------------------------------------------------------------
// Augmentation3d: affine (Rodrigues * scale + shift) + smoothed random
// displacement field + trilinear grid_sample, cropped to center 128^3.
//
// Inputs (metadata order):
//   d_in[0] vol   : (4,1,160,160,160) f32
//   d_in[1] rot   : (4,3) f32
//   d_in[2] scale : (4,3) f32
//   d_in[3] shift : (4,3) f32
//   d_in[4] dz    : (1,1,15,15,15) f32
//   d_in[5] dy    : (1,1,15,15,15) f32
//   d_in[6] dx    : (1,1,15,15,15) f32
// Output: (4,1,128,128,128) f32
// ---------------------------------------------------------------------------

#define VD 160
#define VSZ (VD * VD * VD)
#define OD 128
#define CROP0 16            // (160-128)/2
#define FDIM 15
#define FN (FDIM * FDIM * FDIM)   // 3375
#define FS 11
#define FS3 (FS * FS * FS)        // 1331
#define NBATCH 4
#define KZ 8                 // z-slices per block in sample kernel
#define SCLF (11.0f / 160.0f)

__device__ float g_field[3][FS3];      // cropped smoothed fields (dz, dy, dx)
__device__ float g_theta[NBATCH * 12]; // per batch: 3 rows of [A0 A1 A2 shift]

// ---------------------------------------------------------------------------
// Prep kernel: 3 blocks (one per field). The 4x clamped 5-tap box smooth is a
// fixed linear operator per axis -> build B^4 (15x15) in smem (redundantly per
// block, it's tiny), then apply as three small separable matmuls with the
// [2:13] crop folded in. Block 0 also computes theta for the 4 batches.
// ---------------------------------------------------------------------------
__global__ void __launch_bounds__(1024) prep_kernel(
        const float* __restrict__ rot,
        const float* __restrict__ scale,
        const float* __restrict__ shift,
        const float* __restrict__ dz,
        const float* __restrict__ dy,
        const float* __restrict__ dx) {
    __shared__ float Bm[FDIM][FDIM];   // clamped box matrix
    __shared__ float B2[FDIM][FDIM];   // B^2
    __shared__ float M[FS][FDIM];      // rows 2..12 of B^4 (crop folded)
    __shared__ float bufA[FN];         // 3375
    __shared__ float bufB[FS * FDIM * FDIM]; // 2475

    const int f = blockIdx.x;
    const float* raw = (f == 0) ? dz : ((f == 1) ? dy : dx);
    const int t = threadIdx.x;
    const int NT = blockDim.x;

    // --- theta (block 0, threads 0..3) ---
    if (f == 0 && t < NBATCH) {
        const int nb = t;
        float rx = rot[nb * 3 + 0], ry = rot[nb * 3 + 1], rz = rot[nb * 3 + 2];
        float t2 = rx * rx + ry * ry + rz * rz;
        float th = sqrtf(fmaxf(t2, 1e-6f));
        float inv = 1.0f / (th + 1e-6f);
        float wx = rx * inv, wy = ry * inv, wz = rz * inv;
        float c = cosf(th), s = sinf(th), k = 1.0f - c;
        float R[9];
        if (t2 > 1e-6f) {
            R[0] = c + wx * wx * k;      R[1] = wx * wy * k - wz * s; R[2] = wy * s + wx * wz * k;
            R[3] = wz * s + wx * wy * k; R[4] = c + wy * wy * k;      R[5] = -wx * s + wy * wz * k;
            R[6] = -wy * s + wx * wz * k; R[7] = wx * s + wy * wz * k; R[8] = c + wz * wz * k;
        } else {
            R[0] = 1.0f; R[1] = -rz;  R[2] = ry;
            R[3] = rz;   R[4] = 1.0f; R[5] = -rx;
            R[6] = -ry;  R[7] = rx;   R[8] = 1.0f;
        }
        #pragma unroll
        for (int i = 0; i < 3; ++i) {
            #pragma unroll
            for (int j = 0; j < 3; ++j)
                g_theta[nb * 12 + i * 4 + j] = R[i * 3 + j] * scale[nb * 3 + j];
            g_theta[nb * 12 + i * 4 + 3] = shift[nb * 3 + i];
        }
    }

    // --- build B (clamped box), B^2, then M = (B^4)[2:13,:] ---
    if (t < FDIM * FDIM) {
        int i = t / FDIM, j = t % FDIM;
        int cnt = 0;
        #pragma unroll
        for (int d = -2; d <= 2; ++d) {
            int k = i + d;
            k = k < 0 ? 0 : (k > FDIM - 1 ? FDIM - 1 : k);
            cnt += (k == j);
        }
        Bm[i][j] = 0.2f * (float)cnt;
    }
    // load + pre-scale raw field concurrently
    for (int i = t; i < FN; i += NT)
        bufA[i] = (raw[i] - 0.5f) * 4.0f;       // (raw-0.5)*2*ALPHA
    __syncthreads();
    if (t < FDIM * FDIM) {
        int i = t / FDIM, j = t % FDIM;
        float s = 0.0f;
        #pragma unroll
        for (int k = 0; k < FDIM; ++k) s += Bm[i][k] * Bm[k][j];
        B2[i][j] = s;
    }
    __syncthreads();
    if (t < FS * FDIM) {
        int i = t / FDIM + 2, j = t % FDIM;   // rows 2..12
        float s = 0.0f;
        #pragma unroll
        for (int k = 0; k < FDIM; ++k) s += B2[i][k] * B2[k][j];
        M[i - 2][j] = s;
    }
    __syncthreads();

    // z-pass: [15,15,15] -> [11,15,15]
    for (int i = t; i < FS * FDIM * FDIM; i += NT) {
        int xy = i % (FDIM * FDIM);
        int zo = i / (FDIM * FDIM);
        float s = 0.0f;
        #pragma unroll
        for (int k = 0; k < FDIM; ++k)
            s += M[zo][k] * bufA[k * FDIM * FDIM + xy];
        bufB[i] = s;
    }
    __syncthreads();
    // y-pass: [11,15,15] -> [11,11,15] (into bufA)
    for (int i = t; i < FS * FS * FDIM; i += NT) {
        int x = i % FDIM;
        int yo = (i / FDIM) % FS;
        int zo = i / (FDIM * FS);
        float s = 0.0f;
        #pragma unroll
        for (int k = 0; k < FDIM; ++k)
            s += M[yo][k] * bufB[zo * FDIM * FDIM + k * FDIM + x];
        bufA[zo * FS * FDIM + yo * FDIM + x] = s;
    }
    __syncthreads();
    // x-pass: [11,11,15] -> [11,11,11] (to global)
    for (int i = t; i < FS3; i += NT) {
        int xo = i % FS;
        int yo = (i / FS) % FS;
        int zo = i / (FS * FS);
        float s = 0.0f;
        #pragma unroll
        for (int k = 0; k < FDIM; ++k)
            s += M[xo][k] * bufA[zo * FS * FDIM + yo * FDIM + k];
        g_field[f][i] = s;
    }
}

// ---------------------------------------------------------------------------
// Main kernel: block = one x-row (128 threads) x KZ z-slices. ALL field rows
// for the KZ slices are staged up front behind a single __syncthreads (264
// items, <=3 per thread), pre-scaled by 80 and packed as float4 per x-cell.
// The kz loop then runs barrier-free -> the 8 iterations are independent and
// the compiler can keep ~64 LDG in flight per thread to hide memory latency.
// Interior warps take an unpredicated LDG fast path (warp vote).
// ---------------------------------------------------------------------------
__global__ void __launch_bounds__(128) sample_kernel(
    const float* __restrict__ vol, float* __restrict__ out) {
    const int x  = threadIdx.x;              // 0..127
    const int y  = blockIdx.y;               // 0..127
    const int g  = blockIdx.z;               // n*(128/KZ) + zgrp
    const int n  = g >> 4;                   // 128/KZ = 16
    const int zb = (g & 15) * KZ;            // output z base

    const int xg  = x + CROP0;
    const int yg  = y + CROP0;
    const int zgb = zb + CROP0;

    __shared__ float4 Gf4[KZ][12];           // staged field rows (x80)

    // field y (block-uniform, loop-invariant)
    const float ysrc = fmaf((float)yg + 0.5f, SCLF, -0.5f);
    const int   iy0  = (int)ysrc;
    const float wy   = ysrc - (float)iy0;

    // ---- stage all KZ field rows: 3 fields x 11 x-cells x KZ z = 264 items ----
    for (int s = threadIdx.x; s < 3 * FS * KZ; s += 128) {
        int f2 = s / (FS * KZ);              // field 0..2
        int r  = s - f2 * FS * KZ;
        int kz = r / FS;
        int ix = r - kz * FS;
        float zsrc = fmaf((float)(zgb + kz) + 0.5f, SCLF, -0.5f);
        int   iz0  = (int)zsrc;
        float wz   = zsrc - (float)iz0;
        const float* F = g_field[f2] + (iz0 * FS + iy0) * FS + ix;
        float v00 = __ldg(F);
        float v01 = __ldg(F + FS);
        float v10 = __ldg(F + FS * FS);
        float v11 = __ldg(F + FS * FS + FS);
        float a = fmaf(v01 - v00, wy, v00);
        float b = fmaf(v11 - v10, wy, v10);
        ((float*)&Gf4[kz][ix])[f2] = fmaf(b - a, wz, a) * 80.0f;
    }

    // theta (broadcast loads, loop-invariant) — overlaps with staging
    const float* T = g_theta + n * 12;
    const float t0 = __ldg(T + 0), t1 = __ldg(T + 1), t2 = __ldg(T + 2),  t3  = __ldg(T + 3);
    const float t4 = __ldg(T + 4), t5 = __ldg(T + 5), t6 = __ldg(T + 6),  t7  = __ldg(T + 7);
    const float t8 = __ldg(T + 8), t9 = __ldg(T + 9), t10= __ldg(T + 10), t11 = __ldg(T + 11);

    const float C2 = 2.0f / 160.0f;
    const float C1 = 1.0f / 160.0f - 1.0f;
    const float xv  = fmaf((float)xg,  C2, C1);
    const float yv  = fmaf((float)yg,  C2, C1);
    const float zv0 = fmaf((float)zgb, C2, C1);

    // px = 80*gx + 79.5 ; per-z step of 80*t*(2/160) = t folds to +kz*t2 etc.
    const float bx = fmaf(80.0f, fmaf(t0, xv, fmaf(t1, yv, fmaf(t2,  zv0, t3 ))), 79.5f);
    const float by = fmaf(80.0f, fmaf(t4, xv, fmaf(t5, yv, fmaf(t6,  zv0, t7 ))), 79.5f);
    const float bz = fmaf(80.0f, fmaf(t8, xv, fmaf(t9, yv, fmaf(t10, zv0, t11))), 79.5f);

    // field x-cell (per thread, loop-invariant; interior -> no clamp needed)
    const float xsrc = fmaf((float)xg + 0.5f, SCLF, -0.5f);   // in (0.6, 9.4)
    const int   ix0  = (int)xsrc;
    const float wxf  = xsrc - (float)ix0;

    const float* v  = vol + (size_t)n * VSZ;
    float*       op = out + (((size_t)(n * OD + zb)) * OD + y) * OD + x;

    __syncthreads();   // single barrier: staged rows ready

    #pragma unroll
    for (int kz = 0; kz < KZ; ++kz) {
        float4 A = Gf4[kz][ix0];
        float4 B = Gf4[kz][ix0 + 1];
        float kf = (float)kz;
        float px = fmaf(kf, t2,  bx) + fmaf(B.x - A.x, wxf, A.x);
        float py = fmaf(kf, t6,  by) + fmaf(B.y - A.y, wxf, A.y);
        float pz = fmaf(kf, t10, bz) + fmaf(B.z - A.z, wxf, A.z);

        int x0 = __float2int_rd(px);  float ax = px - (float)x0;
        int y0 = __float2int_rd(py);  float ay = py - (float)y0;
        int z0 = __float2int_rd(pz);  float az = pz - (float)z0;

        const float* vb = v + (z0 * VD + y0) * VD + x0;
        float v000, v001, v010, v011, v100, v101, v110, v111;

        // interior iff 0 <= c <= VD-2 for all axes (covers both corners)
        int inb = ((unsigned)x0 < (unsigned)(VD - 1)) &
                  ((unsigned)y0 < (unsigned)(VD - 1)) &
                  ((unsigned)z0 < (unsigned)(VD - 1));
        if (__all_sync(0xffffffffu, inb)) {
            v000 = __ldg(vb);                    v001 = __ldg(vb + 1);
            v010 = __ldg(vb + VD);               v011 = __ldg(vb + VD + 1);
            v100 = __ldg(vb + VD * VD);          v101 = __ldg(vb + VD * VD + 1);
            v110 = __ldg(vb + VD * VD + VD);     v111 = __ldg(vb + VD * VD + VD + 1);
        } else {
            int vx0 = ((unsigned)x0 < (unsigned)VD);
            int vx1 = ((unsigned)(x0 + 1) < (unsigned)VD);
            int vy0 = ((unsigned)y0 < (unsigned)VD);
            int vy1 = ((unsigned)(y0 + 1) < (unsigned)VD);
            int vz0 = ((unsigned)z0 < (unsigned)VD);
            int vz1 = ((unsigned)(z0 + 1) < (unsigned)VD);
            int p00 = vz0 & vy0, p01 = vz0 & vy1, p10 = vz1 & vy0, p11 = vz1 & vy1;
            v000 = (p00 & vx0) ? __ldg(vb)                    : 0.0f;
            v001 = (p00 & vx1) ? __ldg(vb + 1)                : 0.0f;
            v010 = (p01 & vx0) ? __ldg(vb + VD)               : 0.0f;
            v011 = (p01 & vx1) ? __ldg(vb + VD + 1)           : 0.0f;
            v100 = (p10 & vx0) ? __ldg(vb + VD * VD)          : 0.0f;
            v101 = (p10 & vx1) ? __ldg(vb + VD * VD + 1)      : 0.0f;
            v110 = (p11 & vx0) ? __ldg(vb + VD * VD + VD)     : 0.0f;
            v111 = (p11 & vx1) ? __ldg(vb + VD * VD + VD + 1) : 0.0f;
        }

        // nested-lerp trilinear blend
        float c00 = fmaf(v001 - v000, ax, v000);
        float c01 = fmaf(v011 - v010, ax, v010);
        float c10 = fmaf(v101 - v100, ax, v100);
        float c11 = fmaf(v111 - v110, ax, v110);
        float c0  = fmaf(c01 - c00, ay, c00);
        float c1  = fmaf(c11 - c10, ay, c10);
        float r   = fmaf(c1 - c0, az, c0);

        op[kz * OD * OD] = r;
    }
}

// ---------------------------------------------------------------------------
extern "C" void kernel_launch(void* const* d_in, const int* in_sizes, int n_in,
                              void* d_out, int out_size) {
    const float* vol   = (const float*)d_in[0];
    const float* rot   = (const float*)d_in[1];
    const float* scale = (const float*)d_in[2];
    const float* shift = (const float*)d_in[3];
    const float* dz    = (const float*)d_in[4];
    const float* dy    = (const float*)d_in[5];
    const float* dx    = (const float*)d_in[6];
    float* out = (float*)d_out;

    prep_kernel<<<3, 1024>>>(rot, scale, shift, dz, dy, dx);

    dim3 grid(1, OD, NBATCH * (OD / KZ));
    sample_kernel<<<grid, 128>>>(vol, out);
}

// round 10
// speedup vs baseline: 1.6096x; 1.0410x over previous
#include <cuda_runtime.h>
#include <math.h>

// ---------------------------------------------------------------------------
// Augmentation3d: affine (Rodrigues * scale + shift) + smoothed random
// displacement field + trilinear grid_sample, cropped to center 128^3.
//
// Inputs (metadata order):
//   d_in[0] vol   : (4,1,160,160,160) f32
//   d_in[1] rot   : (4,3) f32
//   d_in[2] scale : (4,3) f32
//   d_in[3] shift : (4,3) f32
//   d_in[4] dz    : (1,1,15,15,15) f32
//   d_in[5] dy    : (1,1,15,15,15) f32
//   d_in[6] dx    : (1,1,15,15,15) f32
// Output: (4,1,128,128,128) f32
// ---------------------------------------------------------------------------

#define VD 160
#define VD2 (VD * VD)
#define VSZ (VD * VD * VD)
#define OD 128
#define CROP0 16            // (160-128)/2
#define FDIM 15
#define FN (FDIM * FDIM * FDIM)   // 3375
#define FS 11
#define FS3 (FS * FS * FS)        // 1331
#define NBATCH 4
#define KZ 8                 // z-slices per block in sample kernel
#define KB 4                 // kz batch size (loads hoisted per batch)
#define SCLF (11.0f / 160.0f)

__device__ float g_field[3][FS3];      // cropped smoothed fields (dz, dy, dx)
__device__ float g_theta[NBATCH * 12]; // per batch: 3 rows of [A0 A1 A2 shift]

// ---------------------------------------------------------------------------
// Prep kernel: 3 blocks (one per field). The 4x clamped 5-tap box smooth is a
// fixed linear operator per axis -> build B^4 (15x15) in smem (redundantly per
// block, it's tiny), then apply as three small separable matmuls with the
// [2:13] crop folded in. Block 0 also computes theta for the 4 batches.
// ---------------------------------------------------------------------------
__global__ void __launch_bounds__(1024) prep_kernel(
        const float* __restrict__ rot,
        const float* __restrict__ scale,
        const float* __restrict__ shift,
        const float* __restrict__ dz,
        const float* __restrict__ dy,
        const float* __restrict__ dx) {
    __shared__ float Bm[FDIM][FDIM];   // clamped box matrix
    __shared__ float B2[FDIM][FDIM];   // B^2
    __shared__ float M[FS][FDIM];      // rows 2..12 of B^4 (crop folded)
    __shared__ float bufA[FN];         // 3375
    __shared__ float bufB[FS * FDIM * FDIM]; // 2475

    const int f = blockIdx.x;
    const float* raw = (f == 0) ? dz : ((f == 1) ? dy : dx);
    const int t = threadIdx.x;
    const int NT = blockDim.x;

    // --- theta (block 0, threads 0..3) ---
    if (f == 0 && t < NBATCH) {
        const int nb = t;
        float rx = rot[nb * 3 + 0], ry = rot[nb * 3 + 1], rz = rot[nb * 3 + 2];
        float t2 = rx * rx + ry * ry + rz * rz;
        float th = sqrtf(fmaxf(t2, 1e-6f));
        float inv = 1.0f / (th + 1e-6f);
        float wx = rx * inv, wy = ry * inv, wz = rz * inv;
        float c = cosf(th), s = sinf(th), k = 1.0f - c;
        float R[9];
        if (t2 > 1e-6f) {
            R[0] = c + wx * wx * k;      R[1] = wx * wy * k - wz * s; R[2] = wy * s + wx * wz * k;
            R[3] = wz * s + wx * wy * k; R[4] = c + wy * wy * k;      R[5] = -wx * s + wy * wz * k;
            R[6] = -wy * s + wx * wz * k; R[7] = wx * s + wy * wz * k; R[8] = c + wz * wz * k;
        } else {
            R[0] = 1.0f; R[1] = -rz;  R[2] = ry;
            R[3] = rz;   R[4] = 1.0f; R[5] = -rx;
            R[6] = -ry;  R[7] = rx;   R[8] = 1.0f;
        }
        #pragma unroll
        for (int i = 0; i < 3; ++i) {
            #pragma unroll
            for (int j = 0; j < 3; ++j)
                g_theta[nb * 12 + i * 4 + j] = R[i * 3 + j] * scale[nb * 3 + j];
            g_theta[nb * 12 + i * 4 + 3] = shift[nb * 3 + i];
        }
    }

    // --- build B (clamped box), B^2, then M = (B^4)[2:13,:] ---
    if (t < FDIM * FDIM) {
        int i = t / FDIM, j = t % FDIM;
        int cnt = 0;
        #pragma unroll
        for (int d = -2; d <= 2; ++d) {
            int k = i + d;
            k = k < 0 ? 0 : (k > FDIM - 1 ? FDIM - 1 : k);
            cnt += (k == j);
        }
        Bm[i][j] = 0.2f * (float)cnt;
    }
    // load + pre-scale raw field concurrently
    for (int i = t; i < FN; i += NT)
        bufA[i] = (raw[i] - 0.5f) * 4.0f;       // (raw-0.5)*2*ALPHA
    __syncthreads();
    if (t < FDIM * FDIM) {
        int i = t / FDIM, j = t % FDIM;
        float s = 0.0f;
        #pragma unroll
        for (int k = 0; k < FDIM; ++k) s += Bm[i][k] * Bm[k][j];
        B2[i][j] = s;
    }
    __syncthreads();
    if (t < FS * FDIM) {
        int i = t / FDIM + 2, j = t % FDIM;   // rows 2..12
        float s = 0.0f;
        #pragma unroll
        for (int k = 0; k < FDIM; ++k) s += B2[i][k] * B2[k][j];
        M[i - 2][j] = s;
    }
    __syncthreads();

    // z-pass: [15,15,15] -> [11,15,15]
    for (int i = t; i < FS * FDIM * FDIM; i += NT) {
        int xy = i % (FDIM * FDIM);
        int zo = i / (FDIM * FDIM);
        float s = 0.0f;
        #pragma unroll
        for (int k = 0; k < FDIM; ++k)
            s += M[zo][k] * bufA[k * FDIM * FDIM + xy];
        bufB[i] = s;
    }
    __syncthreads();
    // y-pass: [11,15,15] -> [11,11,15] (into bufA)
    for (int i = t; i < FS * FS * FDIM; i += NT) {
        int x = i % FDIM;
        int yo = (i / FDIM) % FS;
        int zo = i / (FDIM * FS);
        float s = 0.0f;
        #pragma unroll
        for (int k = 0; k < FDIM; ++k)
            s += M[yo][k] * bufB[zo * FDIM * FDIM + k * FDIM + x];
        bufA[zo * FS * FDIM + yo * FDIM + x] = s;
    }
    __syncthreads();
    // x-pass: [11,11,15] -> [11,11,11] (to global)
    for (int i = t; i < FS3; i += NT) {
        int xo = i % FS;
        int yo = (i / FS) % FS;
        int zo = i / (FS * FS);
        float s = 0.0f;
        #pragma unroll
        for (int k = 0; k < FDIM; ++k)
            s += M[xo][k] * bufA[zo * FS * FDIM + yo * FDIM + k];
        g_field[f][i] = s;
    }
}

// ---------------------------------------------------------------------------
// Main kernel: block = one x-row (128 threads) x KZ z-slices. ALL field rows
// staged up front behind one __syncthreads. The kz loop runs in batches of
// KB=4: coordinates + base pointers for the whole batch, ONE warp vote, then
// (fast path) all 32 gather LDGs issued back-to-back before any blend ->
// MLP per warp ~32 to hide L2/DRAM latency. Slow path handles borders with
// per-corner predicated loads.
// ---------------------------------------------------------------------------
__global__ void __launch_bounds__(128) sample_kernel(
    const float* __restrict__ vol, float* __restrict__ out) {
    const int x  = threadIdx.x;              // 0..127
    const int y  = blockIdx.y;               // 0..127
    const int g  = blockIdx.z;               // n*(128/KZ) + zgrp
    const int n  = g >> 4;                   // 128/KZ = 16
    const int zb = (g & 15) * KZ;            // output z base

    const int xg  = x + CROP0;
    const int yg  = y + CROP0;
    const int zgb = zb + CROP0;

    __shared__ float4 Gf4[KZ][12];           // staged field rows (x80)

    // field y (block-uniform, loop-invariant)
    const float ysrc = fmaf((float)yg + 0.5f, SCLF, -0.5f);
    const int   iy0  = (int)ysrc;
    const float wy   = ysrc - (float)iy0;

    // ---- stage all KZ field rows: 3 fields x 11 x-cells x KZ z = 264 items ----
    for (int s = threadIdx.x; s < 3 * FS * KZ; s += 128) {
        int f2 = s / (FS * KZ);              // field 0..2
        int r  = s - f2 * FS * KZ;
        int kz = r / FS;
        int ix = r - kz * FS;
        float zsrc = fmaf((float)(zgb + kz) + 0.5f, SCLF, -0.5f);
        int   iz0  = (int)zsrc;
        float wz   = zsrc - (float)iz0;
        const float* F = g_field[f2] + (iz0 * FS + iy0) * FS + ix;
        float v00 = __ldg(F);
        float v01 = __ldg(F + FS);
        float v10 = __ldg(F + FS * FS);
        float v11 = __ldg(F + FS * FS + FS);
        float a = fmaf(v01 - v00, wy, v00);
        float b = fmaf(v11 - v10, wy, v10);
        ((float*)&Gf4[kz][ix])[f2] = fmaf(b - a, wz, a) * 80.0f;
    }

    // theta (broadcast loads, loop-invariant) — overlaps with staging
    const float* T = g_theta + n * 12;
    const float t0 = __ldg(T + 0), t1 = __ldg(T + 1), t2 = __ldg(T + 2),  t3  = __ldg(T + 3);
    const float t4 = __ldg(T + 4), t5 = __ldg(T + 5), t6 = __ldg(T + 6),  t7  = __ldg(T + 7);
    const float t8 = __ldg(T + 8), t9 = __ldg(T + 9), t10= __ldg(T + 10), t11 = __ldg(T + 11);

    const float C2 = 2.0f / 160.0f;
    const float C1 = 1.0f / 160.0f - 1.0f;
    const float xv  = fmaf((float)xg,  C2, C1);
    const float yv  = fmaf((float)yg,  C2, C1);
    const float zv0 = fmaf((float)zgb, C2, C1);

    // px = 80*gx + 79.5 ; per-z step of 80*t*(2/160) = t folds to +kz*t2 etc.
    const float bx = fmaf(80.0f, fmaf(t0, xv, fmaf(t1, yv, fmaf(t2,  zv0, t3 ))), 79.5f);
    const float by = fmaf(80.0f, fmaf(t4, xv, fmaf(t5, yv, fmaf(t6,  zv0, t7 ))), 79.5f);
    const float bz = fmaf(80.0f, fmaf(t8, xv, fmaf(t9, yv, fmaf(t10, zv0, t11))), 79.5f);

    // field x-cell (per thread, loop-invariant; interior -> no clamp needed)
    const float xsrc = fmaf((float)xg + 0.5f, SCLF, -0.5f);   // in (0.6, 9.4)
    const int   ix0  = (int)xsrc;
    const float wxf  = xsrc - (float)ix0;

    const float* v  = vol + (size_t)n * VSZ;
    float*       op = out + (((size_t)(n * OD + zb)) * OD + y) * OD + x;

    __syncthreads();   // single barrier: staged rows ready

    #pragma unroll
    for (int b = 0; b < KZ; b += KB) {
        float axA[KB], ayA[KB], azA[KB];
        int   x0A[KB], y0A[KB], z0A[KB];
        const float* vbA[KB];
        int allin = 1;

        #pragma unroll
        for (int j = 0; j < KB; ++j) {
            int kz = b + j;
            float4 A = Gf4[kz][ix0];
            float4 B = Gf4[kz][ix0 + 1];
            float kf = (float)kz;
            float px = fmaf(kf, t2,  bx) + fmaf(B.x - A.x, wxf, A.x);
            float py = fmaf(kf, t6,  by) + fmaf(B.y - A.y, wxf, A.y);
            float pz = fmaf(kf, t10, bz) + fmaf(B.z - A.z, wxf, A.z);
            int x0 = __float2int_rd(px);  axA[j] = px - (float)x0;
            int y0 = __float2int_rd(py);  ayA[j] = py - (float)y0;
            int z0 = __float2int_rd(pz);  azA[j] = pz - (float)z0;
            x0A[j] = x0; y0A[j] = y0; z0A[j] = z0;
            vbA[j] = v + (z0 * VD + y0) * VD + x0;
            allin &= ((unsigned)x0 < (unsigned)(VD - 1)) &
                     ((unsigned)y0 < (unsigned)(VD - 1)) &
                     ((unsigned)z0 < (unsigned)(VD - 1));
        }

        if (__all_sync(0xffffffffu, allin)) {
            // fast path: issue all KB*8 gathers before any blend (MLP ~32)
            float vv[KB][8];
            #pragma unroll
            for (int j = 0; j < KB; ++j) {
                const float* vb = vbA[j];
                vv[j][0] = __ldg(vb);             vv[j][1] = __ldg(vb + 1);
                vv[j][2] = __ldg(vb + VD);        vv[j][3] = __ldg(vb + VD + 1);
                vv[j][4] = __ldg(vb + VD2);       vv[j][5] = __ldg(vb + VD2 + 1);
                vv[j][6] = __ldg(vb + VD2 + VD);  vv[j][7] = __ldg(vb + VD2 + VD + 1);
            }
            #pragma unroll
            for (int j = 0; j < KB; ++j) {
                float ax = axA[j], ay = ayA[j], az = azA[j];
                float c00 = fmaf(vv[j][1] - vv[j][0], ax, vv[j][0]);
                float c01 = fmaf(vv[j][3] - vv[j][2], ax, vv[j][2]);
                float c10 = fmaf(vv[j][5] - vv[j][4], ax, vv[j][4]);
                float c11 = fmaf(vv[j][7] - vv[j][6], ax, vv[j][6]);
                float c0  = fmaf(c01 - c00, ay, c00);
                float c1  = fmaf(c11 - c10, ay, c10);
                op[(b + j) * OD * OD] = fmaf(c1 - c0, az, c0);
            }
        } else {
            // slow path: per-corner predicated loads (borders)
            #pragma unroll
            for (int j = 0; j < KB; ++j) {
                int x0 = x0A[j], y0 = y0A[j], z0 = z0A[j];
                const float* vb = vbA[j];
                int vx0 = ((unsigned)x0 < (unsigned)VD);
                int vx1 = ((unsigned)(x0 + 1) < (unsigned)VD);
                int vy0 = ((unsigned)y0 < (unsigned)VD);
                int vy1 = ((unsigned)(y0 + 1) < (unsigned)VD);
                int vz0 = ((unsigned)z0 < (unsigned)VD);
                int vz1 = ((unsigned)(z0 + 1) < (unsigned)VD);
                int p00 = vz0 & vy0, p01 = vz0 & vy1, p10 = vz1 & vy0, p11 = vz1 & vy1;
                float v000 = (p00 & vx0) ? __ldg(vb)                : 0.0f;
                float v001 = (p00 & vx1) ? __ldg(vb + 1)            : 0.0f;
                float v010 = (p01 & vx0) ? __ldg(vb + VD)           : 0.0f;
                float v011 = (p01 & vx1) ? __ldg(vb + VD + 1)       : 0.0f;
                float v100 = (p10 & vx0) ? __ldg(vb + VD2)          : 0.0f;
                float v101 = (p10 & vx1) ? __ldg(vb + VD2 + 1)      : 0.0f;
                float v110 = (p11 & vx0) ? __ldg(vb + VD2 + VD)     : 0.0f;
                float v111 = (p11 & vx1) ? __ldg(vb + VD2 + VD + 1) : 0.0f;
                float ax = axA[j], ay = ayA[j], az = azA[j];
                float c00 = fmaf(v001 - v000, ax, v000);
                float c01 = fmaf(v011 - v010, ax, v010);
                float c10 = fmaf(v101 - v100, ax, v100);
                float c11 = fmaf(v111 - v110, ax, v110);
                float c0  = fmaf(c01 - c00, ay, c00);
                float c1  = fmaf(c11 - c10, ay, c10);
                op[(b + j) * OD * OD] = fmaf(c1 - c0, az, c0);
            }
        }
    }
}

// ---------------------------------------------------------------------------
extern "C" void kernel_launch(void* const* d_in, const int* in_sizes, int n_in,
                              void* d_out, int out_size) {
    const float* vol   = (const float*)d_in[0];
    const float* rot   = (const float*)d_in[1];
    const float* scale = (const float*)d_in[2];
    const float* shift = (const float*)d_in[3];
    const float* dz    = (const float*)d_in[4];
    const float* dy    = (const float*)d_in[5];
    const float* dx    = (const float*)d_in[6];
    float* out = (float*)d_out;

    prep_kernel<<<3, 1024>>>(rot, scale, shift, dz, dy, dx);

    dim3 grid(1, OD, NBATCH * (OD / KZ));
    sample_kernel<<<grid, 128>>>(vol, out);
}

// round 12
// speedup vs baseline: 1.7646x; 1.0963x over previous
#include <cuda_runtime.h>
#include <math.h>

// ---------------------------------------------------------------------------
// Augmentation3d: affine (Rodrigues * scale + shift) + smoothed random
// displacement field + trilinear grid_sample, cropped to center 128^3.
//
// Inputs (metadata order):
//   d_in[0] vol   : (4,1,160,160,160) f32
//   d_in[1] rot   : (4,3) f32
//   d_in[2] scale : (4,3) f32
//   d_in[3] shift : (4,3) f32
//   d_in[4] dz    : (1,1,15,15,15) f32
//   d_in[5] dy    : (1,1,15,15,15) f32
//   d_in[6] dx    : (1,1,15,15,15) f32
// Output: (4,1,128,128,128) f32
// ---------------------------------------------------------------------------

#define VD 160
#define VD2 (VD * VD)
#define VSZ (VD * VD * VD)
#define OD 128
#define CROP0 16            // (160-128)/2
#define FDIM 15
#define FN (FDIM * FDIM * FDIM)   // 3375
#define FS 11
#define FS3 (FS * FS * FS)        // 1331
#define NBATCH 4
#define KZ 8                 // z-slices per block in sample kernel
#define KB 4                 // kz batch size (loads hoisted per batch)
#define SCLF (11.0f / 160.0f)

__device__ float g_field[3][FS3];      // cropped smoothed fields (dz, dy, dx)
__device__ float g_theta[NBATCH * 12]; // per batch: 3 rows of [A0 A1 A2 shift]

// ---------------------------------------------------------------------------
// Prep kernel: 3 blocks (one per field). The 4x clamped 5-tap box smooth is a
// fixed linear operator per axis -> build B^4 (15x15) in smem (redundantly per
// block, it's tiny), then apply as three small separable matmuls with the
// [2:13] crop folded in. Block 0 also computes theta for the 4 batches.
// ---------------------------------------------------------------------------
__global__ void __launch_bounds__(1024) prep_kernel(
        const float* __restrict__ rot,
        const float* __restrict__ scale,
        const float* __restrict__ shift,
        const float* __restrict__ dz,
        const float* __restrict__ dy,
        const float* __restrict__ dx) {
    __shared__ float Bm[FDIM][FDIM];   // clamped box matrix
    __shared__ float B2[FDIM][FDIM];   // B^2
    __shared__ float M[FS][FDIM];      // rows 2..12 of B^4 (crop folded)
    __shared__ float bufA[FN];         // 3375
    __shared__ float bufB[FS * FDIM * FDIM]; // 2475

    const int f = blockIdx.x;
    const float* raw = (f == 0) ? dz : ((f == 1) ? dy : dx);
    const int t = threadIdx.x;
    const int NT = blockDim.x;

    // --- theta (block 0, threads 0..3) ---
    if (f == 0 && t < NBATCH) {
        const int nb = t;
        float rx = rot[nb * 3 + 0], ry = rot[nb * 3 + 1], rz = rot[nb * 3 + 2];
        float t2 = rx * rx + ry * ry + rz * rz;
        float th = sqrtf(fmaxf(t2, 1e-6f));
        float inv = 1.0f / (th + 1e-6f);
        float wx = rx * inv, wy = ry * inv, wz = rz * inv;
        float c = cosf(th), s = sinf(th), k = 1.0f - c;
        float R[9];
        if (t2 > 1e-6f) {
            R[0] = c + wx * wx * k;      R[1] = wx * wy * k - wz * s; R[2] = wy * s + wx * wz * k;
            R[3] = wz * s + wx * wy * k; R[4] = c + wy * wy * k;      R[5] = -wx * s + wy * wz * k;
            R[6] = -wy * s + wx * wz * k; R[7] = wx * s + wy * wz * k; R[8] = c + wz * wz * k;
        } else {
            R[0] = 1.0f; R[1] = -rz;  R[2] = ry;
            R[3] = rz;   R[4] = 1.0f; R[5] = -rx;
            R[6] = -ry;  R[7] = rx;   R[8] = 1.0f;
        }
        #pragma unroll
        for (int i = 0; i < 3; ++i) {
            #pragma unroll
            for (int j = 0; j < 3; ++j)
                g_theta[nb * 12 + i * 4 + j] = R[i * 3 + j] * scale[nb * 3 + j];
            g_theta[nb * 12 + i * 4 + 3] = shift[nb * 3 + i];
        }
    }

    // --- build B (clamped box), B^2, then M = (B^4)[2:13,:] ---
    if (t < FDIM * FDIM) {
        int i = t / FDIM, j = t % FDIM;
        int cnt = 0;
        #pragma unroll
        for (int d = -2; d <= 2; ++d) {
            int k = i + d;
            k = k < 0 ? 0 : (k > FDIM - 1 ? FDIM - 1 : k);
            cnt += (k == j);
        }
        Bm[i][j] = 0.2f * (float)cnt;
    }
    // load + pre-scale raw field concurrently
    for (int i = t; i < FN; i += NT)
        bufA[i] = (raw[i] - 0.5f) * 4.0f;       // (raw-0.5)*2*ALPHA
    __syncthreads();
    if (t < FDIM * FDIM) {
        int i = t / FDIM, j = t % FDIM;
        float s = 0.0f;
        #pragma unroll
        for (int k = 0; k < FDIM; ++k) s += Bm[i][k] * Bm[k][j];
        B2[i][j] = s;
    }
    __syncthreads();
    if (t < FS * FDIM) {
        int i = t / FDIM + 2, j = t % FDIM;   // rows 2..12
        float s = 0.0f;
        #pragma unroll
        for (int k = 0; k < FDIM; ++k) s += B2[i][k] * B2[k][j];
        M[i - 2][j] = s;
    }
    __syncthreads();

    // z-pass: [15,15,15] -> [11,15,15]
    for (int i = t; i < FS * FDIM * FDIM; i += NT) {
        int xy = i % (FDIM * FDIM);
        int zo = i / (FDIM * FDIM);
        float s = 0.0f;
        #pragma unroll
        for (int k = 0; k < FDIM; ++k)
            s += M[zo][k] * bufA[k * FDIM * FDIM + xy];
        bufB[i] = s;
    }
    __syncthreads();
    // y-pass: [11,15,15] -> [11,11,15] (into bufA)
    for (int i = t; i < FS * FS * FDIM; i += NT) {
        int x = i % FDIM;
        int yo = (i / FDIM) % FS;
        int zo = i / (FDIM * FS);
        float s = 0.0f;
        #pragma unroll
        for (int k = 0; k < FDIM; ++k)
            s += M[yo][k] * bufB[zo * FDIM * FDIM + k * FDIM + x];
        bufA[zo * FS * FDIM + yo * FDIM + x] = s;
    }
    __syncthreads();
    // x-pass: [11,11,15] -> [11,11,11] (to global)
    for (int i = t; i < FS3; i += NT) {
        int xo = i % FS;
        int yo = (i / FS) % FS;
        int zo = i / (FS * FS);
        float s = 0.0f;
        #pragma unroll
        for (int k = 0; k < FDIM; ++k)
            s += M[xo][k] * bufA[zo * FS * FDIM + yo * FDIM + k];
        g_field[f][i] = s;
    }
}

// ---------------------------------------------------------------------------
// Main kernel: block = one x-row (128 threads) x KZ z-slices. All field rows
// staged behind one __syncthreads. kz runs in batches of KB=4 with all
// gathers issued back-to-back (MLP ~32). NEW: z-face reuse — since the source
// z advances by ~1 per kz while x0/y0 drift slowly, iteration j's TOP face
// (z0,y0,x0) frequently equals iteration j-1's BOTTOM face (z0'+1,y0',x0').
// Top-face loads are predicated off on a per-thread face-match and the values
// selected from the previous bottom face (carried across batches), shrinking
// the L1tex wavefront footprint of half the gathers.
// ---------------------------------------------------------------------------
__global__ void __launch_bounds__(128) sample_kernel(
    const float* __restrict__ vol, float* __restrict__ out) {
    const int x  = threadIdx.x;              // 0..127
    const int y  = blockIdx.y;               // 0..127
    const int g  = blockIdx.z;               // n*(128/KZ) + zgrp
    const int n  = g >> 4;                   // 128/KZ = 16
    const int zb = (g & 15) * KZ;            // output z base

    const int xg  = x + CROP0;
    const int yg  = y + CROP0;
    const int zgb = zb + CROP0;

    __shared__ float4 Gf4[KZ][12];           // staged field rows (x80)

    // field y (block-uniform, loop-invariant)
    const float ysrc = fmaf((float)yg + 0.5f, SCLF, -0.5f);
    const int   iy0  = (int)ysrc;
    const float wy   = ysrc - (float)iy0;

    // ---- stage all KZ field rows: 3 fields x 11 x-cells x KZ z = 264 items ----
    for (int s = threadIdx.x; s < 3 * FS * KZ; s += 128) {
        int f2 = s / (FS * KZ);              // field 0..2
        int r  = s - f2 * FS * KZ;
        int kz = r / FS;
        int ix = r - kz * FS;
        float zsrc = fmaf((float)(zgb + kz) + 0.5f, SCLF, -0.5f);
        int   iz0  = (int)zsrc;
        float wz   = zsrc - (float)iz0;
        const float* F = g_field[f2] + (iz0 * FS + iy0) * FS + ix;
        float v00 = __ldg(F);
        float v01 = __ldg(F + FS);
        float v10 = __ldg(F + FS * FS);
        float v11 = __ldg(F + FS * FS + FS);
        float a = fmaf(v01 - v00, wy, v00);
        float b = fmaf(v11 - v10, wy, v10);
        ((float*)&Gf4[kz][ix])[f2] = fmaf(b - a, wz, a) * 80.0f;
    }

    // theta (broadcast loads, loop-invariant) — overlaps with staging
    const float* T = g_theta + n * 12;
    const float t0 = __ldg(T + 0), t1 = __ldg(T + 1), t2 = __ldg(T + 2),  t3  = __ldg(T + 3);
    const float t4 = __ldg(T + 4), t5 = __ldg(T + 5), t6 = __ldg(T + 6),  t7  = __ldg(T + 7);
    const float t8 = __ldg(T + 8), t9 = __ldg(T + 9), t10= __ldg(T + 10), t11 = __ldg(T + 11);

    const float C2 = 2.0f / 160.0f;
    const float C1 = 1.0f / 160.0f - 1.0f;
    const float xv  = fmaf((float)xg,  C2, C1);
    const float yv  = fmaf((float)yg,  C2, C1);
    const float zv0 = fmaf((float)zgb, C2, C1);

    // px = 80*gx + 79.5 ; per-z step of 80*t*(2/160) = t folds to +kz*t2 etc.
    const float bx = fmaf(80.0f, fmaf(t0, xv, fmaf(t1, yv, fmaf(t2,  zv0, t3 ))), 79.5f);
    const float by = fmaf(80.0f, fmaf(t4, xv, fmaf(t5, yv, fmaf(t6,  zv0, t7 ))), 79.5f);
    const float bz = fmaf(80.0f, fmaf(t8, xv, fmaf(t9, yv, fmaf(t10, zv0, t11))), 79.5f);

    // field x-cell (per thread, loop-invariant; interior -> no clamp needed)
    const float xsrc = fmaf((float)xg + 0.5f, SCLF, -0.5f);   // in (0.6, 9.4)
    const int   ix0  = (int)xsrc;
    const float wxf  = xsrc - (float)ix0;

    const float* v  = vol + (size_t)n * VSZ;
    float*       op = out + (((size_t)(n * OD + zb)) * OD + y) * OD + x;

    // cross-batch carry: coords + bottom-face values of last processed iter
    int   xp = 0, yp = 0, zp = -0x40000000;   // impossible -> no reuse on first
    float pb0 = 0.0f, pb1 = 0.0f, pb2 = 0.0f, pb3 = 0.0f;

    __syncthreads();   // single barrier: staged rows ready

    #pragma unroll
    for (int b = 0; b < KZ; b += KB) {
        float axA[KB], ayA[KB], azA[KB];
        int   x0A[KB], y0A[KB], z0A[KB];
        int   ru[KB];
        const float* vbA[KB];
        int allin = 1;

        #pragma unroll
        for (int j = 0; j < KB; ++j) {
            int kz = b + j;
            float4 A = Gf4[kz][ix0];
            float4 B = Gf4[kz][ix0 + 1];
            float kf = (float)kz;
            float px = fmaf(kf, t2,  bx) + fmaf(B.x - A.x, wxf, A.x);
            float py = fmaf(kf, t6,  by) + fmaf(B.y - A.y, wxf, A.y);
            float pz = fmaf(kf, t10, bz) + fmaf(B.z - A.z, wxf, A.z);
            int x0 = __float2int_rd(px);  axA[j] = px - (float)x0;
            int y0 = __float2int_rd(py);  ayA[j] = py - (float)y0;
            int z0 = __float2int_rd(pz);  azA[j] = pz - (float)z0;
            x0A[j] = x0; y0A[j] = y0; z0A[j] = z0;
            vbA[j] = v + (z0 * VD + y0) * VD + x0;
            int px_ = (j == 0) ? xp : x0A[j - 1];
            int py_ = (j == 0) ? yp : y0A[j - 1];
            int pz_ = (j == 0) ? zp : z0A[j - 1];
            ru[j] = (x0 == px_) & (y0 == py_) & (z0 == pz_ + 1);
            allin &= ((unsigned)x0 < (unsigned)(VD - 1)) &
                     ((unsigned)y0 < (unsigned)(VD - 1)) &
                     ((unsigned)z0 < (unsigned)(VD - 1));
        }

        if (__all_sync(0xffffffffu, allin)) {
            // fast path: top-face loads predicated off when reusable; all
            // gathers issued before any blend (MLP ~32 minus reused ones)
            float vt[KB][4], vbt[KB][4];
            #pragma unroll
            for (int j = 0; j < KB; ++j) {
                const float* vb = vbA[j];
                int lr = !ru[j];
                vt[j][0] = 0.0f; vt[j][1] = 0.0f; vt[j][2] = 0.0f; vt[j][3] = 0.0f;
                if (lr) {
                    vt[j][0] = __ldg(vb);        vt[j][1] = __ldg(vb + 1);
                    vt[j][2] = __ldg(vb + VD);   vt[j][3] = __ldg(vb + VD + 1);
                }
                vbt[j][0] = __ldg(vb + VD2);      vbt[j][1] = __ldg(vb + VD2 + 1);
                vbt[j][2] = __ldg(vb + VD2 + VD); vbt[j][3] = __ldg(vb + VD2 + VD + 1);
            }
            #pragma unroll
            for (int j = 0; j < KB; ++j) {
                float p0 = (j == 0) ? pb0 : vbt[j - 1][0];
                float p1 = (j == 0) ? pb1 : vbt[j - 1][1];
                float p2 = (j == 0) ? pb2 : vbt[j - 1][2];
                float p3 = (j == 0) ? pb3 : vbt[j - 1][3];
                float v000 = ru[j] ? p0 : vt[j][0];
                float v001 = ru[j] ? p1 : vt[j][1];
                float v010 = ru[j] ? p2 : vt[j][2];
                float v011 = ru[j] ? p3 : vt[j][3];
                float ax = axA[j], ay = ayA[j], az = azA[j];
                float c00 = fmaf(v001 - v000, ax, v000);
                float c01 = fmaf(v011 - v010, ax, v010);
                float c10 = fmaf(vbt[j][1] - vbt[j][0], ax, vbt[j][0]);
                float c11 = fmaf(vbt[j][3] - vbt[j][2], ax, vbt[j][2]);
                float c0  = fmaf(c01 - c00, ay, c00);
                float c1  = fmaf(c11 - c10, ay, c10);
                op[(b + j) * OD * OD] = fmaf(c1 - c0, az, c0);
            }
            pb0 = vbt[KB - 1][0]; pb1 = vbt[KB - 1][1];
            pb2 = vbt[KB - 1][2]; pb3 = vbt[KB - 1][3];
        } else {
            // slow path: per-corner predicated loads (borders), no reuse
            #pragma unroll
            for (int j = 0; j < KB; ++j) {
                int x0 = x0A[j], y0 = y0A[j], z0 = z0A[j];
                const float* vb = vbA[j];
                int vx0 = ((unsigned)x0 < (unsigned)VD);
                int vx1 = ((unsigned)(x0 + 1) < (unsigned)VD);
                int vy0 = ((unsigned)y0 < (unsigned)VD);
                int vy1 = ((unsigned)(y0 + 1) < (unsigned)VD);
                int vz0 = ((unsigned)z0 < (unsigned)VD);
                int vz1 = ((unsigned)(z0 + 1) < (unsigned)VD);
                int p00 = vz0 & vy0, p01 = vz0 & vy1, p10 = vz1 & vy0, p11 = vz1 & vy1;
                float v000 = (p00 & vx0) ? __ldg(vb)                : 0.0f;
                float v001 = (p00 & vx1) ? __ldg(vb + 1)            : 0.0f;
                float v010 = (p01 & vx0) ? __ldg(vb + VD)           : 0.0f;
                float v011 = (p01 & vx1) ? __ldg(vb + VD + 1)       : 0.0f;
                float v100 = (p10 & vx0) ? __ldg(vb + VD2)          : 0.0f;
                float v101 = (p10 & vx1) ? __ldg(vb + VD2 + 1)      : 0.0f;
                float v110 = (p11 & vx0) ? __ldg(vb + VD2 + VD)     : 0.0f;
                float v111 = (p11 & vx1) ? __ldg(vb + VD2 + VD + 1) : 0.0f;
                float ax = axA[j], ay = ayA[j], az = azA[j];
                float c00 = fmaf(v001 - v000, ax, v000);
                float c01 = fmaf(v011 - v010, ax, v010);
                float c10 = fmaf(v101 - v100, ax, v100);
                float c11 = fmaf(v111 - v110, ax, v110);
                float c0  = fmaf(c01 - c00, ay, c00);
                float c1  = fmaf(c11 - c10, ay, c10);
                op[(b + j) * OD * OD] = fmaf(c1 - c0, az, c0);
                if (j == KB - 1) { pb0 = v100; pb1 = v101; pb2 = v110; pb3 = v111; }
            }
        }
        xp = x0A[KB - 1]; yp = y0A[KB - 1]; zp = z0A[KB - 1];
    }
}

// ---------------------------------------------------------------------------
extern "C" void kernel_launch(void* const* d_in, const int* in_sizes, int n_in,
                              void* d_out, int out_size) {
    const float* vol   = (const float*)d_in[0];
    const float* rot   = (const float*)d_in[1];
    const float* scale = (const float*)d_in[2];
    const float* shift = (const float*)d_in[3];
    const float* dz    = (const float*)d_in[4];
    const float* dy    = (const float*)d_in[5];
    const float* dx    = (const float*)d_in[6];
    float* out = (float*)d_out;

    prep_kernel<<<3, 1024>>>(rot, scale, shift, dz, dy, dx);

    dim3 grid(1, OD, NBATCH * (OD / KZ));
    sample_kernel<<<grid, 128>>>(vol, out);
}